// round 1
// baseline (speedup 1.0000x reference)
#include <cuda_runtime.h>
#include <math.h>

// Shapes (fixed for this problem):
// x: (B=4, C=512, H=64, W=64) -> N = 4096 pixels
// Wf/Wg/Wh: (Cp=64, C=512), Wv: (C=512, Cp=64)
// uf/ug/uh: (64), uv: (512), gamma: (1)

// ---------------- scratch (device globals; no allocation allowed) ----------------
__device__ float g_Wsn[4][64 * 512];                     // spectral-normalized weights
__device__ float g_fgh[3 * 4 * 64 * 4096];               // fx, gx, hx  (w, b, cp, n)
__device__ float g_S[(size_t)4 * 4096 * 4096];           // raw scores (b, i, j)  256 MB
__device__ float g_m[4 * 4096];                          // row max
__device__ float g_zinv[4 * 4096];                       // 1 / row sum exp
__device__ float g_attout[4 * 64 * 4096];                // attention output (b, cp, j)

// ---------------- spectral norm: W_sn = W / (u^T W v),  v = normalize(W^T u) ----------------
__global__ void spectral_kernel(const float* Wf, const float* Wg, const float* Wh, const float* Wv,
                                const float* uf, const float* ug, const float* uh, const float* uv)
{
    int w = blockIdx.x;
    const float* W; const float* u; int R, Cc;
    if      (w == 0) { W = Wf; u = uf; R = 64;  Cc = 512; }
    else if (w == 1) { W = Wg; u = ug; R = 64;  Cc = 512; }
    else if (w == 2) { W = Wh; u = uh; R = 64;  Cc = 512; }
    else             { W = Wv; u = uv; R = 512; Cc = 64;  }
    float* Wsn = g_Wsn[w];

    __shared__ float sv[512];
    __shared__ float red[512];
    __shared__ float s_scalar;
    int tid = threadIdx.x;   // 512 threads

    // v = W^T u
    float vv = 0.f;
    if (tid < Cc) {
        float s = 0.f;
        for (int r = 0; r < R; ++r) s += W[r * Cc + tid] * u[r];
        sv[tid] = s;
        vv = s * s;
    }
    red[tid] = vv;
    __syncthreads();
    for (int off = 256; off > 0; off >>= 1) {
        if (tid < off) red[tid] += red[tid + off];
        __syncthreads();
    }
    if (tid == 0) s_scalar = 1.0f / (sqrtf(red[0]) + 1e-12f);
    __syncthreads();
    if (tid < Cc) sv[tid] *= s_scalar;
    __syncthreads();

    // sigma = u^T (W v)
    float part = 0.f;
    if (tid < R) {
        float s = 0.f;
        for (int c = 0; c < Cc; ++c) s += W[tid * Cc + c] * sv[c];
        part = u[tid] * s;
    }
    red[tid] = part;
    __syncthreads();
    for (int off = 256; off > 0; off >>= 1) {
        if (tid < off) red[tid] += red[tid + off];
        __syncthreads();
    }
    if (tid == 0) s_scalar = 1.0f / red[0];
    __syncthreads();
    float is = s_scalar;
    for (int idx = tid; idx < R * Cc; idx += 512) Wsn[idx] = W[idx] * is;
}

// ---------------- projections: fgh[w][b] = Wsn[w] (64x512) @ x[b] (512x4096) ----------------
__global__ void proj_kernel(const float* x)
{
    int w  = blockIdx.z;
    int b  = blockIdx.y;
    int n0 = blockIdx.x * 64;
    const float* A  = g_Wsn[w];                        // 64 x 512 row-major
    const float* Bx = x + (size_t)b * 512 * 4096;      // 512 x 4096
    float* Cout = g_fgh + (size_t)(w * 4 + b) * 64 * 4096;

    __shared__ float As[32][65];
    __shared__ float Bs[32][65];
    int tid = threadIdx.x;
    int ty = tid >> 4, tx = tid & 15;
    float acc[4][4] = {};

    for (int k0 = 0; k0 < 512; k0 += 32) {
        #pragma unroll
        for (int t = 0; t < 8; ++t) {
            int idx = tid + t * 256;
            int m = idx >> 5, k = idx & 31;
            As[k][m] = A[m * 512 + k0 + k];
        }
        #pragma unroll
        for (int t = 0; t < 8; ++t) {
            int idx = tid + t * 256;
            int k = idx >> 6, n = idx & 63;
            Bs[k][n] = Bx[(size_t)(k0 + k) * 4096 + n0 + n];
        }
        __syncthreads();
        #pragma unroll
        for (int kk = 0; kk < 32; ++kk) {
            float a[4], bb[4];
            #pragma unroll
            for (int i = 0; i < 4; ++i) { a[i] = As[kk][ty * 4 + i]; bb[i] = Bs[kk][tx * 4 + i]; }
            #pragma unroll
            for (int mi = 0; mi < 4; ++mi)
                #pragma unroll
                for (int ni = 0; ni < 4; ++ni)
                    acc[mi][ni] = fmaf(a[mi], bb[ni], acc[mi][ni]);
        }
        __syncthreads();
    }
    #pragma unroll
    for (int mi = 0; mi < 4; ++mi)
        #pragma unroll
        for (int ni = 0; ni < 4; ++ni)
            Cout[(size_t)(ty * 4 + mi) * 4096 + n0 + tx * 4 + ni] = acc[mi][ni];
}

// ---------------- scores: S[b,i,j] = sum_cp fx[b,cp,i] * gx[b,cp,j] ----------------
__global__ void scores_kernel()
{
    int b  = blockIdx.z;
    int i0 = blockIdx.y * 64;
    int j0 = blockIdx.x * 64;
    const float* fx = g_fgh + (size_t)(0 * 4 + b) * 64 * 4096;
    const float* gx = g_fgh + (size_t)(1 * 4 + b) * 64 * 4096;
    float* S = g_S + (size_t)b * 4096 * 4096;

    __shared__ float As[32][65];
    __shared__ float Bs[32][65];
    int tid = threadIdx.x;
    int ty = tid >> 4, tx = tid & 15;
    float acc[4][4] = {};

    for (int k0 = 0; k0 < 64; k0 += 32) {
        #pragma unroll
        for (int t = 0; t < 8; ++t) {
            int idx = tid + t * 256;
            int k = idx >> 6, n = idx & 63;
            As[k][n] = fx[(size_t)(k0 + k) * 4096 + i0 + n];
            Bs[k][n] = gx[(size_t)(k0 + k) * 4096 + j0 + n];
        }
        __syncthreads();
        #pragma unroll
        for (int kk = 0; kk < 32; ++kk) {
            float a[4], bb[4];
            #pragma unroll
            for (int i = 0; i < 4; ++i) { a[i] = As[kk][ty * 4 + i]; bb[i] = Bs[kk][tx * 4 + i]; }
            #pragma unroll
            for (int mi = 0; mi < 4; ++mi)
                #pragma unroll
                for (int ni = 0; ni < 4; ++ni)
                    acc[mi][ni] = fmaf(a[mi], bb[ni], acc[mi][ni]);
        }
        __syncthreads();
    }
    #pragma unroll
    for (int mi = 0; mi < 4; ++mi)
        #pragma unroll
        for (int ni = 0; ni < 4; ++ni)
            S[(size_t)(i0 + ty * 4 + mi) * 4096 + j0 + tx * 4 + ni] = acc[mi][ni];
}

// ---------------- row stats: m_i = max_j S, Z_i = sum_j exp(S - m_i) ----------------
__global__ void stats_kernel()
{
    int b = blockIdx.y, i = blockIdx.x;
    const float* row = g_S + ((size_t)b * 4096 + i) * 4096;
    int tid = threadIdx.x;   // 256
    float m = -INFINITY, z = 0.f;
    for (int j = tid; j < 4096; j += 256) {
        float s = row[j];
        if (s > m) { z = z * expf(m - s) + 1.0f; m = s; }
        else        z += expf(s - m);
    }
    __shared__ float sm[256], sz[256];
    sm[tid] = m; sz[tid] = z;
    __syncthreads();
    for (int off = 128; off > 0; off >>= 1) {
        if (tid < off) {
            float m1 = sm[tid], z1 = sz[tid];
            float m2 = sm[tid + off], z2 = sz[tid + off];
            float M = fmaxf(m1, m2);
            sm[tid] = M;
            sz[tid] = z1 * expf(m1 - M) + z2 * expf(m2 - M);
        }
        __syncthreads();
    }
    if (tid == 0) {
        g_m[b * 4096 + i]    = sm[0];
        g_zinv[b * 4096 + i] = 1.0f / sz[0];
    }
}

// ---------------- PV: out[b,c,j] = sum_i (hx[b,c,i]/Z_i) * exp(S[b,i,j] - m_i) ----------------
__global__ void pv_kernel()
{
    int b  = blockIdx.y;
    int j0 = blockIdx.x * 64;
    const float* hx   = g_fgh + (size_t)(2 * 4 + b) * 64 * 4096;
    const float* S    = g_S + (size_t)b * 4096 * 4096;
    const float* mrow = g_m + b * 4096;
    const float* zrow = g_zinv + b * 4096;
    float* Cout = g_attout + (size_t)b * 64 * 4096;

    __shared__ float As[32][65];
    __shared__ float Bs[32][65];
    int tid = threadIdx.x;
    int ty = tid >> 4, tx = tid & 15;
    float acc[4][4] = {};

    for (int k0 = 0; k0 < 4096; k0 += 32) {
        #pragma unroll
        for (int t = 0; t < 8; ++t) {
            int idx = tid + t * 256;
            int m = idx >> 5, k = idx & 31;
            As[k][m] = hx[(size_t)m * 4096 + k0 + k] * zrow[k0 + k];
        }
        #pragma unroll
        for (int t = 0; t < 8; ++t) {
            int idx = tid + t * 256;
            int k = idx >> 6, n = idx & 63;
            Bs[k][n] = expf(S[(size_t)(k0 + k) * 4096 + j0 + n] - mrow[k0 + k]);
        }
        __syncthreads();
        #pragma unroll
        for (int kk = 0; kk < 32; ++kk) {
            float a[4], bb[4];
            #pragma unroll
            for (int i = 0; i < 4; ++i) { a[i] = As[kk][ty * 4 + i]; bb[i] = Bs[kk][tx * 4 + i]; }
            #pragma unroll
            for (int mi = 0; mi < 4; ++mi)
                #pragma unroll
                for (int ni = 0; ni < 4; ++ni)
                    acc[mi][ni] = fmaf(a[mi], bb[ni], acc[mi][ni]);
        }
        __syncthreads();
    }
    #pragma unroll
    for (int mi = 0; mi < 4; ++mi)
        #pragma unroll
        for (int ni = 0; ni < 4; ++ni)
            Cout[(size_t)(ty * 4 + mi) * 4096 + j0 + tx * 4 + ni] = acc[mi][ni];
}

// ---------------- final: y = gamma * (Wv_sn @ attout) + x ----------------
__global__ void final_kernel(const float* x, const float* gamma, float* y)
{
    int b  = blockIdx.z;
    int c0 = blockIdx.y * 64;
    int n0 = blockIdx.x * 64;
    const float* A  = g_Wsn[3];                               // 512 x 64
    const float* Bv = g_attout + (size_t)b * 64 * 4096;       // 64 x 4096

    __shared__ float As[32][65];
    __shared__ float Bs[32][65];
    int tid = threadIdx.x;
    int ty = tid >> 4, tx = tid & 15;
    float acc[4][4] = {};

    for (int k0 = 0; k0 < 64; k0 += 32) {
        #pragma unroll
        for (int t = 0; t < 8; ++t) {
            int idx = tid + t * 256;
            int m = idx >> 5, k = idx & 31;
            As[k][m] = A[(c0 + m) * 64 + k0 + k];
        }
        #pragma unroll
        for (int t = 0; t < 8; ++t) {
            int idx = tid + t * 256;
            int k = idx >> 6, n = idx & 63;
            Bs[k][n] = Bv[(size_t)(k0 + k) * 4096 + n0 + n];
        }
        __syncthreads();
        #pragma unroll
        for (int kk = 0; kk < 32; ++kk) {
            float a[4], bb[4];
            #pragma unroll
            for (int i = 0; i < 4; ++i) { a[i] = As[kk][ty * 4 + i]; bb[i] = Bs[kk][tx * 4 + i]; }
            #pragma unroll
            for (int mi = 0; mi < 4; ++mi)
                #pragma unroll
                for (int ni = 0; ni < 4; ++ni)
                    acc[mi][ni] = fmaf(a[mi], bb[ni], acc[mi][ni]);
        }
        __syncthreads();
    }
    float g = gamma[0];
    #pragma unroll
    for (int mi = 0; mi < 4; ++mi)
        #pragma unroll
        for (int ni = 0; ni < 4; ++ni) {
            size_t o = (size_t)b * 512 * 4096 + (size_t)(c0 + ty * 4 + mi) * 4096 + n0 + tx * 4 + ni;
            y[o] = g * acc[mi][ni] + x[o];
        }
}

// ---------------- launch ----------------
extern "C" void kernel_launch(void* const* d_in, const int* in_sizes, int n_in,
                              void* d_out, int out_size)
{
    const float* x     = (const float*)d_in[0];
    const float* Wf    = (const float*)d_in[1];
    const float* Wg    = (const float*)d_in[2];
    const float* Wh    = (const float*)d_in[3];
    const float* Wv    = (const float*)d_in[4];
    const float* uf    = (const float*)d_in[5];
    const float* ug    = (const float*)d_in[6];
    const float* uh    = (const float*)d_in[7];
    const float* uv    = (const float*)d_in[8];
    const float* gamma = (const float*)d_in[9];
    float* y = (float*)d_out;

    spectral_kernel<<<4, 512>>>(Wf, Wg, Wh, Wv, uf, ug, uh, uv);
    proj_kernel<<<dim3(64, 4, 3), 256>>>(x);
    scores_kernel<<<dim3(64, 64, 4), 256>>>();
    stats_kernel<<<dim3(4096, 4), 256>>>();
    pv_kernel<<<dim3(64, 4), 256>>>();
    final_kernel<<<dim3(64, 8, 4), 256>>>(x, gamma, y);
}

// round 3
// speedup vs baseline: 3.1000x; 3.1000x over previous
#include <cuda_runtime.h>
#include <cuda_fp16.h>
#include <math.h>
#include <stdint.h>

#define NPIX 4096
#define CIN  512
#define CP   64

// ---------------- scratch ----------------
__device__ __half g_W16[3][CP * CIN];                 // fp16 spectral-normalized Wf/Wg/Wh
__device__ float  g_Wv[CIN * CP];                     // fp32 Wv_sn
__device__ __half g_f[(size_t)4 * CP * NPIX];         // (b, c, n)
__device__ __half g_g[(size_t)4 * CP * NPIX];
__device__ __half g_h[(size_t)4 * CP * NPIX];
__device__ __half g_hsc[(size_t)4 * CP * NPIX];       // h * zinv
__device__ __half g_E[(size_t)4 * NPIX * NPIX];       // exp(S - m), (b, i, j), 128 MB
__device__ float  g_m[4 * NPIX];
__device__ float  g_zinv[4 * NPIX];
__device__ float  g_attout[(size_t)4 * CP * NPIX];    // (b, c, j) fp32

// ---------------- helpers ----------------
__device__ __forceinline__ uint32_t smem_u32(const void* p) {
    uint32_t a;
    asm("{ .reg .u64 t; cvta.to.shared.u64 t, %1; cvt.u32.u64 %0, t; }" : "=r"(a) : "l"(p));
    return a;
}
__device__ __forceinline__ void ldsm_x4(uint32_t* r, uint32_t a) {
    asm volatile("ldmatrix.sync.aligned.m8n8.x4.shared.b16 {%0,%1,%2,%3}, [%4];"
                 : "=r"(r[0]), "=r"(r[1]), "=r"(r[2]), "=r"(r[3]) : "r"(a));
}
__device__ __forceinline__ void ldsm_x4_t(uint32_t* r, uint32_t a) {
    asm volatile("ldmatrix.sync.aligned.m8n8.x4.trans.shared.b16 {%0,%1,%2,%3}, [%4];"
                 : "=r"(r[0]), "=r"(r[1]), "=r"(r[2]), "=r"(r[3]) : "r"(a));
}
__device__ __forceinline__ void mma16816(float* c, const uint32_t* a, uint32_t b0, uint32_t b1) {
    asm volatile("mma.sync.aligned.m16n8k16.row.col.f32.f16.f16.f32 "
                 "{%0,%1,%2,%3}, {%4,%5,%6,%7}, {%8,%9}, {%0,%1,%2,%3};"
                 : "+f"(c[0]), "+f"(c[1]), "+f"(c[2]), "+f"(c[3])
                 : "r"(a[0]), "r"(a[1]), "r"(a[2]), "r"(a[3]), "r"(b0), "r"(b1));
}
__device__ __forceinline__ uint32_t pack2(float a, float b) {
    __half2 h = __floats2half2_rn(a, b);
    return *reinterpret_cast<uint32_t*>(&h);
}
// smem swizzle: row of rowB bytes, 16B chunks, xor low-3 chunk bits with row&7
__device__ __forceinline__ uint32_t swz(int row, int ch, int rowB) {
    return (uint32_t)(row * rowB + ((ch ^ (row & 7)) << 4));
}

// ---------------- spectral norm ----------------
__global__ void spectral_kernel(const float* Wf, const float* Wg, const float* Wh, const float* Wv,
                                const float* uf, const float* ug, const float* uh, const float* uv)
{
    int w = blockIdx.x;
    const float* W; const float* u; int R, Cc;
    if      (w == 0) { W = Wf; u = uf; R = 64;  Cc = 512; }
    else if (w == 1) { W = Wg; u = ug; R = 64;  Cc = 512; }
    else if (w == 2) { W = Wh; u = uh; R = 64;  Cc = 512; }
    else             { W = Wv; u = uv; R = 512; Cc = 64;  }

    __shared__ float sv[512];
    __shared__ float red[512];
    __shared__ float s_scalar;
    int tid = threadIdx.x;

    float vv = 0.f;
    if (tid < Cc) {
        float s = 0.f;
        for (int r = 0; r < R; ++r) s += W[r * Cc + tid] * u[r];
        sv[tid] = s;
        vv = s * s;
    }
    red[tid] = vv;
    __syncthreads();
    for (int off = 256; off > 0; off >>= 1) {
        if (tid < off) red[tid] += red[tid + off];
        __syncthreads();
    }
    if (tid == 0) s_scalar = 1.0f / (sqrtf(red[0]) + 1e-12f);
    __syncthreads();
    if (tid < Cc) sv[tid] *= s_scalar;
    __syncthreads();

    float part = 0.f;
    if (tid < R) {
        float s = 0.f;
        for (int c = 0; c < Cc; ++c) s += W[tid * Cc + c] * sv[c];
        part = u[tid] * s;
    }
    red[tid] = part;
    __syncthreads();
    for (int off = 256; off > 0; off >>= 1) {
        if (tid < off) red[tid] += red[tid + off];
        __syncthreads();
    }
    if (tid == 0) s_scalar = 1.0f / red[0];
    __syncthreads();
    float is = s_scalar;
    if (w < 3) {
        for (int idx = tid; idx < R * Cc; idx += 512) g_W16[w][idx] = __float2half(W[idx] * is);
    } else {
        for (int idx = tid; idx < R * Cc; idx += 512) g_Wv[idx] = W[idx] * is;
    }
}

// ---------------- projections: f/g/h = W16 (64x512) @ x (512x4096), HMMA ----------------
__global__ __launch_bounds__(256, 1) void proj_kernel(const float* x)
{
    __shared__ __align__(16) __half sW[CP * 64];    // 64 rows(c) x 64 cols(k), rowB=128
    __shared__ __align__(16) __half sX[64 * 128];   // 64 rows(k) x 128 cols(n), rowB=256
    const int w = blockIdx.z, b = blockIdx.y, n0 = blockIdx.x * 128;
    const int tid = threadIdx.x, lane = tid & 31, wid = tid >> 5;
    const int mw = wid >> 2, nw = wid & 3;
    const uint32_t sWu = smem_u32(sW), sXu = smem_u32(sX);
    const __half* Wg = g_W16[w];
    const float* xg = x + (size_t)b * CIN * NPIX;

    float c[2][4][4] = {};
    for (int kc = 0; kc < 8; ++kc) {
        #pragma unroll
        for (int p = 0; p < 2; ++p) {
            int slot = tid + p * 256;
            int r = slot >> 3, ch = slot & 7;
            uint4 v = *(const uint4*)(Wg + r * CIN + kc * 64 + ch * 8);
            *(uint4*)((char*)sW + swz(r, ch, 128)) = v;
        }
        #pragma unroll
        for (int p = 0; p < 4; ++p) {
            int slot = tid + p * 256;
            int r = slot >> 4, ch = slot & 15;
            const float4* src = (const float4*)(xg + (size_t)(kc * 64 + r) * NPIX + n0 + ch * 8);
            float4 f0 = src[0], f1 = src[1];
            uint4 v;
            v.x = pack2(f0.x, f0.y); v.y = pack2(f0.z, f0.w);
            v.z = pack2(f1.x, f1.y); v.w = pack2(f1.z, f1.w);
            *(uint4*)((char*)sX + swz(r, ch, 256)) = v;
        }
        __syncthreads();
        #pragma unroll
        for (int kk = 0; kk < 4; ++kk) {
            uint32_t a[2][4];
            #pragma unroll
            for (int ms = 0; ms < 2; ++ms) {
                int m0 = mw * 32 + ms * 16;
                int row = m0 + (lane & 7) + ((lane >> 3) & 1) * 8;
                int ch = kk * 2 + (lane >> 4);
                ldsm_x4(a[ms], sWu + swz(row, ch, 128));
            }
            #pragma unroll
            for (int ng = 0; ng < 2; ++ng) {
                int nb = nw * 32 + ng * 16;
                int row = kk * 16 + (lane & 7) + ((lane >> 3) & 1) * 8;
                int ch = (nb >> 3) + (lane >> 4);
                uint32_t bf[4];
                ldsm_x4_t(bf, sXu + swz(row, ch, 256));
                #pragma unroll
                for (int ms = 0; ms < 2; ++ms) {
                    mma16816(c[ms][ng * 2],     a[ms], bf[0], bf[1]);
                    mma16816(c[ms][ng * 2 + 1], a[ms], bf[2], bf[3]);
                }
            }
        }
        __syncthreads();
    }
    __half* dst = (w == 0 ? g_f : w == 1 ? g_g : g_h) + (size_t)b * CP * NPIX;
    #pragma unroll
    for (int ms = 0; ms < 2; ++ms)
        #pragma unroll
        for (int nt = 0; nt < 4; ++nt) {
            int row = mw * 32 + ms * 16 + (lane >> 2);
            int col = n0 + nw * 32 + (nt >> 1) * 16 + (nt & 1) * 8 + 2 * (lane & 3);
            *(uint32_t*)(dst + (size_t)row * NPIX + col)       = pack2(c[ms][nt][0], c[ms][nt][1]);
            *(uint32_t*)(dst + (size_t)(row + 8) * NPIX + col) = pack2(c[ms][nt][2], c[ms][nt][3]);
        }
}

// ---------------- pass A: row max of S = f^T g (never materialized) ----------------
__global__ __launch_bounds__(256, 1) void rowmax_kernel()
{
    __shared__ __align__(16) __half sF[64 * 128];   // rows c 64 x i 128
    __shared__ __align__(16) __half sG[64 * 128];   // rows c 64 x j 128
    __shared__ float s_red[4][128];
    const int b = blockIdx.y, i0 = blockIdx.x * 128;
    const int tid = threadIdx.x, lane = tid & 31, wid = tid >> 5;
    const int mw = wid >> 2, nw = wid & 3;
    const uint32_t sFu = smem_u32(sF), sGu = smem_u32(sG);
    const __half* F = g_f + (size_t)b * CP * NPIX;
    const __half* G = g_g + (size_t)b * CP * NPIX;

    #pragma unroll
    for (int p = 0; p < 4; ++p) {
        int slot = tid + p * 256;
        int r = slot >> 4, ch = slot & 15;
        uint4 v = *(const uint4*)(F + (size_t)r * NPIX + i0 + ch * 8);
        *(uint4*)((char*)sF + swz(r, ch, 256)) = v;
    }

    uint32_t afr[4][4][4];
    float rm[8];
    #pragma unroll
    for (int q = 0; q < 8; ++q) rm[q] = -INFINITY;

    for (int jc = 0; jc < 32; ++jc) {
        const int j0 = jc * 128;
        #pragma unroll
        for (int p = 0; p < 4; ++p) {
            int slot = tid + p * 256;
            int r = slot >> 4, ch = slot & 15;
            uint4 v = *(const uint4*)(G + (size_t)r * NPIX + j0 + ch * 8);
            *(uint4*)((char*)sG + swz(r, ch, 256)) = v;
        }
        __syncthreads();
        if (jc == 0) {
            #pragma unroll
            for (int ms = 0; ms < 4; ++ms)
                #pragma unroll
                for (int kk = 0; kk < 4; ++kk) {
                    int m0 = mw * 64 + ms * 16;
                    int row = kk * 16 + (lane & 7) + ((lane >> 4) & 1) * 8;
                    int ch = (m0 >> 3) + ((lane >> 3) & 1);
                    ldsm_x4_t(afr[ms][kk], sFu + swz(row, ch, 256));
                }
        }
        float c[4][4][4] = {};
        #pragma unroll
        for (int kk = 0; kk < 4; ++kk) {
            #pragma unroll
            for (int ng = 0; ng < 2; ++ng) {
                int nb = nw * 32 + ng * 16;
                int row = kk * 16 + (lane & 7) + ((lane >> 3) & 1) * 8;
                int ch = (nb >> 3) + (lane >> 4);
                uint32_t bf[4];
                ldsm_x4_t(bf, sGu + swz(row, ch, 256));
                #pragma unroll
                for (int ms = 0; ms < 4; ++ms) {
                    mma16816(c[ms][ng * 2],     afr[ms][kk], bf[0], bf[1]);
                    mma16816(c[ms][ng * 2 + 1], afr[ms][kk], bf[2], bf[3]);
                }
            }
        }
        #pragma unroll
        for (int ms = 0; ms < 4; ++ms)
            #pragma unroll
            for (int nt = 0; nt < 4; ++nt) {
                rm[ms * 2]     = fmaxf(rm[ms * 2],     fmaxf(c[ms][nt][0], c[ms][nt][1]));
                rm[ms * 2 + 1] = fmaxf(rm[ms * 2 + 1], fmaxf(c[ms][nt][2], c[ms][nt][3]));
            }
        __syncthreads();
    }
    #pragma unroll
    for (int q = 0; q < 8; ++q) {
        rm[q] = fmaxf(rm[q], __shfl_xor_sync(0xffffffffu, rm[q], 1));
        rm[q] = fmaxf(rm[q], __shfl_xor_sync(0xffffffffu, rm[q], 2));
    }
    if ((lane & 3) == 0) {
        #pragma unroll
        for (int ms = 0; ms < 4; ++ms) {
            s_red[nw][mw * 64 + ms * 16 + (lane >> 2)]     = rm[ms * 2];
            s_red[nw][mw * 64 + ms * 16 + (lane >> 2) + 8] = rm[ms * 2 + 1];
        }
    }
    __syncthreads();
    if (tid < 128)
        g_m[b * NPIX + i0 + tid] = fmaxf(fmaxf(s_red[0][tid], s_red[1][tid]),
                                         fmaxf(s_red[2][tid], s_red[3][tid]));
}

// ---------------- pass B: E = exp(S - m) (fp16, stored), z = row sums ----------------
__global__ __launch_bounds__(256, 1) void expz_kernel()
{
    __shared__ __align__(16) __half sF[64 * 128];
    __shared__ __align__(16) __half sG[64 * 128];
    __shared__ float s_m[128];
    __shared__ float s_z[4][128];
    const int b = blockIdx.y, i0 = blockIdx.x * 128;
    const int tid = threadIdx.x, lane = tid & 31, wid = tid >> 5;
    const int mw = wid >> 2, nw = wid & 3;
    const uint32_t sFu = smem_u32(sF), sGu = smem_u32(sG);
    const __half* F = g_f + (size_t)b * CP * NPIX;
    const __half* G = g_g + (size_t)b * CP * NPIX;
    __half* Eb = g_E + ((size_t)b << 24);

    #pragma unroll
    for (int p = 0; p < 4; ++p) {
        int slot = tid + p * 256;
        int r = slot >> 4, ch = slot & 15;
        uint4 v = *(const uint4*)(F + (size_t)r * NPIX + i0 + ch * 8);
        *(uint4*)((char*)sF + swz(r, ch, 256)) = v;
    }
    if (tid < 128) s_m[tid] = g_m[b * NPIX + i0 + tid];

    uint32_t afr[4][4][4];
    float mreg[8];
    float z[8] = {};

    for (int jc = 0; jc < 32; ++jc) {
        const int j0 = jc * 128;
        #pragma unroll
        for (int p = 0; p < 4; ++p) {
            int slot = tid + p * 256;
            int r = slot >> 4, ch = slot & 15;
            uint4 v = *(const uint4*)(G + (size_t)r * NPIX + j0 + ch * 8);
            *(uint4*)((char*)sG + swz(r, ch, 256)) = v;
        }
        __syncthreads();
        if (jc == 0) {
            #pragma unroll
            for (int ms = 0; ms < 4; ++ms) {
                #pragma unroll
                for (int kk = 0; kk < 4; ++kk) {
                    int m0 = mw * 64 + ms * 16;
                    int row = kk * 16 + (lane & 7) + ((lane >> 4) & 1) * 8;
                    int ch = (m0 >> 3) + ((lane >> 3) & 1);
                    ldsm_x4_t(afr[ms][kk], sFu + swz(row, ch, 256));
                }
                mreg[ms * 2]     = s_m[mw * 64 + ms * 16 + (lane >> 2)];
                mreg[ms * 2 + 1] = s_m[mw * 64 + ms * 16 + (lane >> 2) + 8];
            }
        }
        float c[4][4][4] = {};
        #pragma unroll
        for (int kk = 0; kk < 4; ++kk) {
            #pragma unroll
            for (int ng = 0; ng < 2; ++ng) {
                int nb = nw * 32 + ng * 16;
                int row = kk * 16 + (lane & 7) + ((lane >> 3) & 1) * 8;
                int ch = (nb >> 3) + (lane >> 4);
                uint32_t bf[4];
                ldsm_x4_t(bf, sGu + swz(row, ch, 256));
                #pragma unroll
                for (int ms = 0; ms < 4; ++ms) {
                    mma16816(c[ms][ng * 2],     afr[ms][kk], bf[0], bf[1]);
                    mma16816(c[ms][ng * 2 + 1], afr[ms][kk], bf[2], bf[3]);
                }
            }
        }
        #pragma unroll
        for (int ms = 0; ms < 4; ++ms) {
            int row = mw * 64 + ms * 16 + (lane >> 2);
            #pragma unroll
            for (int nt = 0; nt < 4; ++nt) {
                int col = j0 + nw * 32 + (nt >> 1) * 16 + (nt & 1) * 8 + 2 * (lane & 3);
                float e0 = __expf(c[ms][nt][0] - mreg[ms * 2]);
                float e1 = __expf(c[ms][nt][1] - mreg[ms * 2]);
                float e2 = __expf(c[ms][nt][2] - mreg[ms * 2 + 1]);
                float e3 = __expf(c[ms][nt][3] - mreg[ms * 2 + 1]);
                z[ms * 2]     += e0 + e1;
                z[ms * 2 + 1] += e2 + e3;
                *(uint32_t*)(Eb + (size_t)(i0 + row) * NPIX + col)     = pack2(e0, e1);
                *(uint32_t*)(Eb + (size_t)(i0 + row + 8) * NPIX + col) = pack2(e2, e3);
            }
        }
        __syncthreads();
    }
    #pragma unroll
    for (int q = 0; q < 8; ++q) {
        z[q] += __shfl_xor_sync(0xffffffffu, z[q], 1);
        z[q] += __shfl_xor_sync(0xffffffffu, z[q], 2);
    }
    if ((lane & 3) == 0) {
        #pragma unroll
        for (int ms = 0; ms < 4; ++ms) {
            s_z[nw][mw * 64 + ms * 16 + (lane >> 2)]     = z[ms * 2];
            s_z[nw][mw * 64 + ms * 16 + (lane >> 2) + 8] = z[ms * 2 + 1];
        }
    }
    __syncthreads();
    if (tid < 128)
        g_zinv[b * NPIX + i0 + tid] =
            1.0f / (s_z[0][tid] + s_z[1][tid] + s_z[2][tid] + s_z[3][tid]);
}

// ---------------- hsc = h * zinv ----------------
__global__ void hscale_kernel()
{
    int idx = blockIdx.x * 256 + threadIdx.x;      // 4*64*4096 = 2^20
    int b = idx >> 18, n = idx & 4095;
    g_hsc[idx] = __float2half(__half2float(g_h[idx]) * g_zinv[b * NPIX + n]);
}

// ---------------- pass C: attout = hsc @ E ----------------
__global__ __launch_bounds__(256, 1) void pv_kernel()
{
    __shared__ __align__(16) __half sH[64 * 64];    // rows c 64 x i 64, rowB=128
    __shared__ __align__(16) __half sE[64 * 128];   // rows i 64 x j 128, rowB=256
    const int b = blockIdx.y, j0 = blockIdx.x * 128;
    const int tid = threadIdx.x, lane = tid & 31, wid = tid >> 5;
    const int mw = wid >> 2, nw = wid & 3;
    const uint32_t sHu = smem_u32(sH), sEu = smem_u32(sE);
    const __half* H = g_hsc + (size_t)b * CP * NPIX;
    const __half* Eb = g_E + ((size_t)b << 24);

    float c[2][4][4] = {};
    for (int ic = 0; ic < 64; ++ic) {
        const int i0 = ic * 64;
        #pragma unroll
        for (int p = 0; p < 2; ++p) {
            int slot = tid + p * 256;
            int r = slot >> 3, ch = slot & 7;
            uint4 v = *(const uint4*)(H + (size_t)r * NPIX + i0 + ch * 8);
            *(uint4*)((char*)sH + swz(r, ch, 128)) = v;
        }
        #pragma unroll
        for (int p = 0; p < 4; ++p) {
            int slot = tid + p * 256;
            int r = slot >> 4, ch = slot & 15;
            uint4 v = *(const uint4*)(Eb + (size_t)(i0 + r) * NPIX + j0 + ch * 8);
            *(uint4*)((char*)sE + swz(r, ch, 256)) = v;
        }
        __syncthreads();
        #pragma unroll
        for (int kk = 0; kk < 4; ++kk) {
            uint32_t a[2][4];
            #pragma unroll
            for (int ms = 0; ms < 2; ++ms) {
                int m0 = mw * 32 + ms * 16;
                int row = m0 + (lane & 7) + ((lane >> 3) & 1) * 8;
                int ch = kk * 2 + (lane >> 4);
                ldsm_x4(a[ms], sHu + swz(row, ch, 128));
            }
            #pragma unroll
            for (int ng = 0; ng < 2; ++ng) {
                int nb = nw * 32 + ng * 16;
                int row = kk * 16 + (lane & 7) + ((lane >> 3) & 1) * 8;
                int ch = (nb >> 3) + (lane >> 4);
                uint32_t bf[4];
                ldsm_x4_t(bf, sEu + swz(row, ch, 256));
                #pragma unroll
                for (int ms = 0; ms < 2; ++ms) {
                    mma16816(c[ms][ng * 2],     a[ms], bf[0], bf[1]);
                    mma16816(c[ms][ng * 2 + 1], a[ms], bf[2], bf[3]);
                }
            }
        }
        __syncthreads();
    }
    float* dst = g_attout + (size_t)b * CP * NPIX;
    #pragma unroll
    for (int ms = 0; ms < 2; ++ms)
        #pragma unroll
        for (int nt = 0; nt < 4; ++nt) {
            int row = mw * 32 + ms * 16 + (lane >> 2);
            int col = j0 + nw * 32 + (nt >> 1) * 16 + (nt & 1) * 8 + 2 * (lane & 3);
            *(float2*)(dst + (size_t)row * NPIX + col)       = make_float2(c[ms][nt][0], c[ms][nt][1]);
            *(float2*)(dst + (size_t)(row + 8) * NPIX + col) = make_float2(c[ms][nt][2], c[ms][nt][3]);
        }
}

// ---------------- final: y = gamma * (Wv_sn @ attout) + x ----------------
__global__ void final_kernel(const float* x, const float* gamma, float* y)
{
    int b  = blockIdx.z;
    int c0 = blockIdx.y * 64;
    int n0 = blockIdx.x * 64;
    const float* A  = g_Wv;                                   // 512 x 64
    const float* Bv = g_attout + (size_t)b * CP * NPIX;       // 64 x 4096

    __shared__ float As[32][65];
    __shared__ float Bs[32][65];
    int tid = threadIdx.x;
    int ty = tid >> 4, tx = tid & 15;
    float acc[4][4] = {};

    for (int k0 = 0; k0 < 64; k0 += 32) {
        #pragma unroll
        for (int t = 0; t < 8; ++t) {
            int idx = tid + t * 256;
            int m = idx >> 5, k = idx & 31;
            As[k][m] = A[(c0 + m) * 64 + k0 + k];
        }
        #pragma unroll
        for (int t = 0; t < 8; ++t) {
            int idx = tid + t * 256;
            int k = idx >> 6, n = idx & 63;
            Bs[k][n] = Bv[(size_t)(k0 + k) * NPIX + n0 + n];
        }
        __syncthreads();
        #pragma unroll
        for (int kk = 0; kk < 32; ++kk) {
            float a[4], bb[4];
            #pragma unroll
            for (int i = 0; i < 4; ++i) { a[i] = As[kk][ty * 4 + i]; bb[i] = Bs[kk][tx * 4 + i]; }
            #pragma unroll
            for (int mi = 0; mi < 4; ++mi)
                #pragma unroll
                for (int ni = 0; ni < 4; ++ni)
                    acc[mi][ni] = fmaf(a[mi], bb[ni], acc[mi][ni]);
        }
        __syncthreads();
    }
    float g = gamma[0];
    #pragma unroll
    for (int mi = 0; mi < 4; ++mi)
        #pragma unroll
        for (int ni = 0; ni < 4; ++ni) {
            size_t o = (size_t)b * CIN * NPIX + (size_t)(c0 + ty * 4 + mi) * NPIX + n0 + tx * 4 + ni;
            y[o] = g * acc[mi][ni] + x[o];
        }
}

// ---------------- launch ----------------
extern "C" void kernel_launch(void* const* d_in, const int* in_sizes, int n_in,
                              void* d_out, int out_size)
{
    const float* x     = (const float*)d_in[0];
    const float* Wf    = (const float*)d_in[1];
    const float* Wg    = (const float*)d_in[2];
    const float* Wh    = (const float*)d_in[3];
    const float* Wv    = (const float*)d_in[4];
    const float* uf    = (const float*)d_in[5];
    const float* ug    = (const float*)d_in[6];
    const float* uh    = (const float*)d_in[7];
    const float* uv    = (const float*)d_in[8];
    const float* gamma = (const float*)d_in[9];
    float* y = (float*)d_out;

    spectral_kernel<<<4, 512>>>(Wf, Wg, Wh, Wv, uf, ug, uh, uv);
    proj_kernel<<<dim3(32, 4, 3), 256>>>(x);
    rowmax_kernel<<<dim3(32, 4), 256>>>();
    expz_kernel<<<dim3(32, 4), 256>>>();
    hscale_kernel<<<4096, 256>>>();
    pv_kernel<<<dim3(32, 4), 256>>>();
    final_kernel<<<dim3(64, 8, 4), 256>>>(x, gamma, y);
}

// round 4
// speedup vs baseline: 3.5204x; 1.1356x over previous
#include <cuda_runtime.h>
#include <cuda_fp16.h>
#include <math.h>
#include <stdint.h>

#define NPIX 4096
#define CIN  512
#define CP   64

// ---------------- scratch ----------------
__device__ __half g_W16[3][CP * CIN];
__device__ float  g_Wv[CIN * CP];
__device__ __half g_f[(size_t)4 * CP * NPIX];         // (b, c, n)
__device__ __half g_g[(size_t)4 * CP * NPIX];
__device__ __half g_h[(size_t)4 * CP * NPIX];
__device__ __half g_hsc[(size_t)4 * CP * NPIX];       // h * zinv
__device__ __half g_E[(size_t)4 * NPIX * NPIX];       // exp(S - m_run), (b,i,j) 128MB
__device__ float  g_mrun[(size_t)4 * NPIX * 128];     // running max per (b,i,stripe32) 8MB
__device__ __half g_r16[(size_t)4 * NPIX * 128];      // exp(m_run - m_fin) 4MB
__device__ float  g_mfin[4 * NPIX];
__device__ float  g_zinv[4 * NPIX];
__device__ float  g_attout[(size_t)4 * CP * NPIX];

// ---------------- helpers ----------------
__device__ __forceinline__ uint32_t smem_u32(const void* p) {
    uint32_t a;
    asm("{ .reg .u64 t; cvta.to.shared.u64 t, %1; cvt.u32.u64 %0, t; }" : "=r"(a) : "l"(p));
    return a;
}
__device__ __forceinline__ void ldsm_x4(uint32_t* r, uint32_t a) {
    asm volatile("ldmatrix.sync.aligned.m8n8.x4.shared.b16 {%0,%1,%2,%3}, [%4];"
                 : "=r"(r[0]), "=r"(r[1]), "=r"(r[2]), "=r"(r[3]) : "r"(a));
}
__device__ __forceinline__ void ldsm_x4_t(uint32_t* r, uint32_t a) {
    asm volatile("ldmatrix.sync.aligned.m8n8.x4.trans.shared.b16 {%0,%1,%2,%3}, [%4];"
                 : "=r"(r[0]), "=r"(r[1]), "=r"(r[2]), "=r"(r[3]) : "r"(a));
}
__device__ __forceinline__ void mma16816(float* c, const uint32_t* a, uint32_t b0, uint32_t b1) {
    asm volatile("mma.sync.aligned.m16n8k16.row.col.f32.f16.f16.f32 "
                 "{%0,%1,%2,%3}, {%4,%5,%6,%7}, {%8,%9}, {%0,%1,%2,%3};"
                 : "+f"(c[0]), "+f"(c[1]), "+f"(c[2]), "+f"(c[3])
                 : "r"(a[0]), "r"(a[1]), "r"(a[2]), "r"(a[3]), "r"(b0), "r"(b1));
}
__device__ __forceinline__ uint32_t pack2(float a, float b) {
    __half2 h = __floats2half2_rn(a, b);
    return *reinterpret_cast<uint32_t*>(&h);
}
__device__ __forceinline__ uint32_t swz(int row, int ch, int rowB) {
    return (uint32_t)(row * rowB + ((ch ^ (row & 7)) << 4));
}
__device__ __forceinline__ void cp16(uint32_t dst, const void* src) {
    asm volatile("{ .reg .u64 g; cvta.to.global.u64 g, %1; cp.async.ca.shared.global [%0], [g], 16; }"
                 :: "r"(dst), "l"(src));
}
#define CP_COMMIT()  asm volatile("cp.async.commit_group;" ::: "memory")
#define CP_WAIT(n)   asm volatile("cp.async.wait_group %0;" :: "n"(n) : "memory")
__device__ __forceinline__ uint32_t hscale2(uint32_t u, __half2 hr) {
    __half2 t = *reinterpret_cast<__half2*>(&u);
    t = __hmul2(t, hr);
    return *reinterpret_cast<uint32_t*>(&t);
}

// ---------------- spectral norm ----------------
__global__ void spectral_kernel(const float* Wf, const float* Wg, const float* Wh, const float* Wv,
                                const float* uf, const float* ug, const float* uh, const float* uv)
{
    int w = blockIdx.x;
    const float* W; const float* u; int R, Cc;
    if      (w == 0) { W = Wf; u = uf; R = 64;  Cc = 512; }
    else if (w == 1) { W = Wg; u = ug; R = 64;  Cc = 512; }
    else if (w == 2) { W = Wh; u = uh; R = 64;  Cc = 512; }
    else             { W = Wv; u = uv; R = 512; Cc = 64;  }

    __shared__ float sv[512];
    __shared__ float red[512];
    __shared__ float s_scalar;
    int tid = threadIdx.x;

    float vv = 0.f;
    if (tid < Cc) {
        float s = 0.f;
        for (int r = 0; r < R; ++r) s += W[r * Cc + tid] * u[r];
        sv[tid] = s;
        vv = s * s;
    }
    red[tid] = vv;
    __syncthreads();
    for (int off = 256; off > 0; off >>= 1) {
        if (tid < off) red[tid] += red[tid + off];
        __syncthreads();
    }
    if (tid == 0) s_scalar = 1.0f / (sqrtf(red[0]) + 1e-12f);
    __syncthreads();
    if (tid < Cc) sv[tid] *= s_scalar;
    __syncthreads();

    float part = 0.f;
    if (tid < R) {
        float s = 0.f;
        for (int c = 0; c < Cc; ++c) s += W[tid * Cc + c] * sv[c];
        part = u[tid] * s;
    }
    red[tid] = part;
    __syncthreads();
    for (int off = 256; off > 0; off >>= 1) {
        if (tid < off) red[tid] += red[tid + off];
        __syncthreads();
    }
    if (tid == 0) s_scalar = 1.0f / red[0];
    __syncthreads();
    float is = s_scalar;
    if (w < 3) {
        for (int idx = tid; idx < R * Cc; idx += 512) g_W16[w][idx] = __float2half(W[idx] * is);
    } else {
        for (int idx = tid; idx < R * Cc; idx += 512) g_Wv[idx] = W[idx] * is;
    }
}

// ---------------- projections: f/g/h = W16 (64x512) @ x (512x4096), HMMA ----------------
__global__ __launch_bounds__(256, 1) void proj_kernel(const float* x)
{
    __shared__ __align__(16) __half sW[CP * 64];    // 64c x 64k, rowB 128
    __shared__ __align__(16) __half sX[64 * 128];   // 64k x 128n, rowB 256
    const int w = blockIdx.z, b = blockIdx.y, n0 = blockIdx.x * 128;
    const int tid = threadIdx.x, lane = tid & 31, wid = tid >> 5;
    const int mw = wid >> 2, nw = wid & 3;
    const uint32_t sWu = smem_u32(sW), sXu = smem_u32(sX);
    const __half* Wg = g_W16[w];
    const float* xg = x + (size_t)b * CIN * NPIX;

    float c[2][4][4] = {};
    for (int kc = 0; kc < 8; ++kc) {
        #pragma unroll
        for (int p = 0; p < 2; ++p) {
            int slot = tid + p * 256;
            int r = slot >> 3, ch = slot & 7;
            uint4 v = *(const uint4*)(Wg + r * CIN + kc * 64 + ch * 8);
            *(uint4*)((char*)sW + swz(r, ch, 128)) = v;
        }
        #pragma unroll
        for (int p = 0; p < 4; ++p) {
            int slot = tid + p * 256;
            int r = slot >> 4, ch = slot & 15;
            const float4* src = (const float4*)(xg + (size_t)(kc * 64 + r) * NPIX + n0 + ch * 8);
            float4 f0 = src[0], f1 = src[1];
            uint4 v;
            v.x = pack2(f0.x, f0.y); v.y = pack2(f0.z, f0.w);
            v.z = pack2(f1.x, f1.y); v.w = pack2(f1.z, f1.w);
            *(uint4*)((char*)sX + swz(r, ch, 256)) = v;
        }
        __syncthreads();
        #pragma unroll
        for (int kk = 0; kk < 4; ++kk) {
            uint32_t a[2][4];
            #pragma unroll
            for (int ms = 0; ms < 2; ++ms) {
                int m0 = mw * 32 + ms * 16;
                int row = m0 + (lane & 7) + ((lane >> 3) & 1) * 8;
                int ch = kk * 2 + (lane >> 4);
                ldsm_x4(a[ms], sWu + swz(row, ch, 128));
            }
            #pragma unroll
            for (int ng = 0; ng < 2; ++ng) {
                int nb = nw * 32 + ng * 16;
                int row = kk * 16 + (lane & 7) + ((lane >> 3) & 1) * 8;
                int ch = (nb >> 3) + (lane >> 4);
                uint32_t bf[4];
                ldsm_x4_t(bf, sXu + swz(row, ch, 256));
                #pragma unroll
                for (int ms = 0; ms < 2; ++ms) {
                    mma16816(c[ms][ng * 2],     a[ms], bf[0], bf[1]);
                    mma16816(c[ms][ng * 2 + 1], a[ms], bf[2], bf[3]);
                }
            }
        }
        __syncthreads();
    }
    __half* dst = (w == 0 ? g_f : w == 1 ? g_g : g_h) + (size_t)b * CP * NPIX;
    #pragma unroll
    for (int ms = 0; ms < 2; ++ms)
        #pragma unroll
        for (int nt = 0; nt < 4; ++nt) {
            int row = mw * 32 + ms * 16 + (lane >> 2);
            int col = n0 + nw * 32 + (nt >> 1) * 16 + (nt & 1) * 8 + 2 * (lane & 3);
            *(uint32_t*)(dst + (size_t)row * NPIX + col)       = pack2(c[ms][nt][0], c[ms][nt][1]);
            *(uint32_t*)(dst + (size_t)(row + 8) * NPIX + col) = pack2(c[ms][nt][2], c[ms][nt][3]);
        }
}

// ---------------- expz (online): E = exp(S - m_run), per-warp running max per 32-j stripe ----------------
// grid (64 i-tiles, 4 b), block 256. i-tile 64.
__global__ __launch_bounds__(256) void expz_kernel()
{
    __shared__ __align__(16) __half sF[64 * 64];        // c64 x i64, rowB 128
    __shared__ __align__(16) __half sG[2][64 * 128];    // c64 x j128, rowB 256, double buffer
    __shared__ float s_mz[4][2][64];
    const int b = blockIdx.y, i0 = blockIdx.x * 64;
    const int tid = threadIdx.x, lane = tid & 31, wid = tid >> 5;
    const int mw = wid >> 2, nw = wid & 3;               // mw: i-half, nw: j 32-stripe
    const uint32_t sFu = smem_u32(sF);
    const uint32_t sGu0 = smem_u32(sG[0]), sGu1 = smem_u32(sG[1]);
    const __half* F = g_f + (size_t)b * CP * NPIX;
    const __half* G = g_g + (size_t)b * CP * NPIX;
    __half* Eb = g_E + ((size_t)b << 24);

    // F tile (once)
    #pragma unroll
    for (int p = 0; p < 2; ++p) {
        int slot = tid + p * 256;
        int r = slot >> 3, ch = slot & 7;
        uint4 v = *(const uint4*)(F + (size_t)r * NPIX + i0 + ch * 8);
        *(uint4*)((char*)sF + swz(r, ch, 128)) = v;
    }
    // prefetch G chunk 0
    #pragma unroll
    for (int p = 0; p < 4; ++p) {
        int slot = tid + p * 256;
        int r = slot >> 4, ch = slot & 15;
        cp16(sGu0 + swz(r, ch, 256), G + (size_t)r * NPIX + ch * 8);
    }
    CP_COMMIT();

    uint32_t afr[2][4][4];
    float m[4], z[4] = {0.f, 0.f, 0.f, 0.f};
    #pragma unroll
    for (int q = 0; q < 4; ++q) m[q] = -INFINITY;

    for (int jc = 0; jc < 32; ++jc) {
        const int j0 = jc * 128;
        if (jc + 1 < 32) {
            uint32_t dstb = (jc & 1) ? sGu0 : sGu1;
            #pragma unroll
            for (int p = 0; p < 4; ++p) {
                int slot = tid + p * 256;
                int r = slot >> 4, ch = slot & 15;
                cp16(dstb + swz(r, ch, 256), G + (size_t)r * NPIX + (j0 + 128) + ch * 8);
            }
            CP_COMMIT();
            CP_WAIT(1);
        } else {
            CP_WAIT(0);
        }
        __syncthreads();
        const uint32_t sGu = (jc & 1) ? sGu1 : sGu0;

        if (jc == 0) {
            #pragma unroll
            for (int ms = 0; ms < 2; ++ms)
                #pragma unroll
                for (int kk = 0; kk < 4; ++kk) {
                    int m0 = mw * 32 + ms * 16;
                    int row = kk * 16 + (lane & 7) + ((lane >> 4) & 1) * 8;
                    int ch = (m0 >> 3) + ((lane >> 3) & 1);
                    ldsm_x4_t(afr[ms][kk], sFu + swz(row, ch, 128));
                }
        }
        float c[2][4][4] = {};
        #pragma unroll
        for (int kk = 0; kk < 4; ++kk) {
            #pragma unroll
            for (int ng = 0; ng < 2; ++ng) {
                int nb = nw * 32 + ng * 16;
                int row = kk * 16 + (lane & 7) + ((lane >> 3) & 1) * 8;
                int ch = (nb >> 3) + (lane >> 4);
                uint32_t bf[4];
                ldsm_x4_t(bf, sGu + swz(row, ch, 256));
                #pragma unroll
                for (int ms = 0; ms < 2; ++ms) {
                    mma16816(c[ms][ng * 2],     afr[ms][kk], bf[0], bf[1]);
                    mma16816(c[ms][ng * 2 + 1], afr[ms][kk], bf[2], bf[3]);
                }
            }
        }
        // per-warp online max update for its 32-j stripe
        float cm[4];
        #pragma unroll
        for (int ms = 0; ms < 2; ++ms) {
            float a0 = fmaxf(fmaxf(c[ms][0][0], c[ms][0][1]), fmaxf(c[ms][1][0], c[ms][1][1]));
            float a1 = fmaxf(fmaxf(c[ms][2][0], c[ms][2][1]), fmaxf(c[ms][3][0], c[ms][3][1]));
            cm[ms * 2] = fmaxf(a0, a1);
            float b0 = fmaxf(fmaxf(c[ms][0][2], c[ms][0][3]), fmaxf(c[ms][1][2], c[ms][1][3]));
            float b1 = fmaxf(fmaxf(c[ms][2][2], c[ms][2][3]), fmaxf(c[ms][3][2], c[ms][3][3]));
            cm[ms * 2 + 1] = fmaxf(b0, b1);
        }
        #pragma unroll
        for (int q = 0; q < 4; ++q) {
            cm[q] = fmaxf(cm[q], __shfl_xor_sync(0xffffffffu, cm[q], 1));
            cm[q] = fmaxf(cm[q], __shfl_xor_sync(0xffffffffu, cm[q], 2));
            float mnew = fmaxf(m[q], cm[q]);
            z[q] *= __expf(m[q] - mnew);
            m[q] = mnew;
        }
        // exp + store E + accumulate z
        #pragma unroll
        for (int ms = 0; ms < 2; ++ms) {
            int row = mw * 32 + ms * 16 + (lane >> 2);
            #pragma unroll
            for (int nt = 0; nt < 4; ++nt) {
                int col = j0 + nw * 32 + (nt >> 1) * 16 + (nt & 1) * 8 + 2 * (lane & 3);
                float e0 = __expf(c[ms][nt][0] - m[ms * 2]);
                float e1 = __expf(c[ms][nt][1] - m[ms * 2]);
                float e2 = __expf(c[ms][nt][2] - m[ms * 2 + 1]);
                float e3 = __expf(c[ms][nt][3] - m[ms * 2 + 1]);
                z[ms * 2]     += e0 + e1;
                z[ms * 2 + 1] += e2 + e3;
                *(uint32_t*)(Eb + (size_t)(i0 + row) * NPIX + col)     = pack2(e0, e1);
                *(uint32_t*)(Eb + (size_t)(i0 + row + 8) * NPIX + col) = pack2(e2, e3);
            }
        }
        // record running max for this (row, stripe)
        if ((lane & 3) == 0) {
            #pragma unroll
            for (int q = 0; q < 4; ++q) {
                int row = mw * 32 + (q >> 1) * 16 + (lane >> 2) + (q & 1) * 8;
                g_mrun[((size_t)(b * NPIX + i0 + row)) * 128 + jc * 4 + nw] = m[q];
            }
        }
        __syncthreads();
    }
    // combine 4 stripe-warps per row
    if ((lane & 3) == 0) {
        #pragma unroll
        for (int q = 0; q < 4; ++q) {
            int row = mw * 32 + (q >> 1) * 16 + (lane >> 2) + (q & 1) * 8;
            s_mz[nw][0][row] = m[q];
            s_mz[nw][1][row] = z[q];
        }
    }
    __syncthreads();
    if (tid < 64) {
        float m0 = s_mz[0][0][tid], m1 = s_mz[1][0][tid], m2 = s_mz[2][0][tid], m3 = s_mz[3][0][tid];
        float mf = fmaxf(fmaxf(m0, m1), fmaxf(m2, m3));
        float Z = s_mz[0][1][tid] * __expf(m0 - mf) + s_mz[1][1][tid] * __expf(m1 - mf)
                + s_mz[2][1][tid] * __expf(m2 - mf) + s_mz[3][1][tid] * __expf(m3 - mf);
        g_mfin[b * NPIX + i0 + tid] = mf;
        g_zinv[b * NPIX + i0 + tid] = 1.0f / Z;
    }
}

// ---------------- corr: r = exp(m_run - m_fin) as fp16 ----------------
__global__ void corr_kernel()
{
    int idx = blockIdx.x * 256 + threadIdx.x;   // 4*4096*128 = 2^21
    int bi = idx >> 7;
    g_r16[idx] = __float2half(__expf(g_mrun[idx] - g_mfin[bi]));
}

// ---------------- hsc = h * zinv ----------------
__global__ void hscale_kernel()
{
    int idx = blockIdx.x * 256 + threadIdx.x;   // 2^20
    int b = idx >> 18, n = idx & 4095;
    g_hsc[idx] = __float2half(__half2float(g_h[idx]) * g_zinv[b * NPIX + n]);
}

// ---------------- pv: attout = hsc @ (E * r) ----------------
// grid (64 j-tiles, 4 b), block 256. j-tile 64, K = i in chunks of 64.
__global__ __launch_bounds__(256) void pv_kernel()
{
    __shared__ __align__(16) __half sH[64 * 64];   // c64 x i64, rowB 128
    __shared__ __align__(16) __half sE[64 * 64];   // i64 x j64, rowB 128
    const int b = blockIdx.y, j0 = blockIdx.x * 64;
    const int tid = threadIdx.x, lane = tid & 31, wid = tid >> 5;
    const int mw = wid >> 2, nw = wid & 3;
    const uint32_t sHu = smem_u32(sH), sEu = smem_u32(sE);
    const __half* H = g_hsc + (size_t)b * CP * NPIX;
    const __half* Eb = g_E + ((size_t)b << 24);
    const __half* Rb = g_r16 + ((size_t)b * NPIX) * 128 + (j0 >> 5);

    const int r_row = tid >> 3, r_ch = tid & 7;    // slot p=0 mapping
    const int r_row1 = (tid + 256) >> 3, r_ch1 = (tid + 256) & 7;

    uint4 vH[2], vE[2];
    __half rr[2];
    // prologue: ic = 0
    vH[0] = *(const uint4*)(H + (size_t)r_row  * NPIX + r_ch  * 8);
    vH[1] = *(const uint4*)(H + (size_t)r_row1 * NPIX + r_ch1 * 8);
    vE[0] = *(const uint4*)(Eb + (size_t)r_row  * NPIX + j0 + r_ch  * 8);
    vE[1] = *(const uint4*)(Eb + (size_t)r_row1 * NPIX + j0 + r_ch1 * 8);
    rr[0] = Rb[(size_t)r_row  * 128 + (r_ch  >> 2)];
    rr[1] = Rb[(size_t)r_row1 * 128 + (r_ch1 >> 2)];

    float c[2][2][4] = {};
    for (int ic = 0; ic < 64; ++ic) {
        const int i0 = ic * 64;
        // store current tiles
        *(uint4*)((char*)sH + swz(r_row,  r_ch,  128)) = vH[0];
        *(uint4*)((char*)sH + swz(r_row1, r_ch1, 128)) = vH[1];
        {
            __half2 h0 = __half2half2(rr[0]), h1 = __half2half2(rr[1]);
            uint4 e0 = vE[0], e1 = vE[1];
            e0.x = hscale2(e0.x, h0); e0.y = hscale2(e0.y, h0);
            e0.z = hscale2(e0.z, h0); e0.w = hscale2(e0.w, h0);
            e1.x = hscale2(e1.x, h1); e1.y = hscale2(e1.y, h1);
            e1.z = hscale2(e1.z, h1); e1.w = hscale2(e1.w, h1);
            *(uint4*)((char*)sE + swz(r_row,  r_ch,  128)) = e0;
            *(uint4*)((char*)sE + swz(r_row1, r_ch1, 128)) = e1;
        }
        __syncthreads();
        // prefetch next
        if (ic + 1 < 64) {
            const int i1 = i0 + 64;
            vH[0] = *(const uint4*)(H + (size_t)r_row  * NPIX + i1 + r_ch  * 8);
            vH[1] = *(const uint4*)(H + (size_t)r_row1 * NPIX + i1 + r_ch1 * 8);
            vE[0] = *(const uint4*)(Eb + (size_t)(i1 + r_row)  * NPIX + j0 + r_ch  * 8);
            vE[1] = *(const uint4*)(Eb + (size_t)(i1 + r_row1) * NPIX + j0 + r_ch1 * 8);
            rr[0] = Rb[(size_t)(i1 + r_row)  * 128 + (r_ch  >> 2)];
            rr[1] = Rb[(size_t)(i1 + r_row1) * 128 + (r_ch1 >> 2)];
        }
        // MMA
        #pragma unroll
        for (int kk = 0; kk < 4; ++kk) {
            uint32_t bf[4];
            {
                int row = kk * 16 + (lane & 7) + ((lane >> 3) & 1) * 8;
                int ch = nw * 2 + (lane >> 4);
                ldsm_x4_t(bf, sEu + swz(row, ch, 128));
            }
            #pragma unroll
            for (int ms = 0; ms < 2; ++ms) {
                uint32_t a[4];
                int m0 = mw * 32 + ms * 16;
                int row = m0 + (lane & 7) + ((lane >> 3) & 1) * 8;
                int ch = kk * 2 + (lane >> 4);
                ldsm_x4(a, sHu + swz(row, ch, 128));
                mma16816(c[ms][0], a, bf[0], bf[1]);
                mma16816(c[ms][1], a, bf[2], bf[3]);
            }
        }
        __syncthreads();
    }
    float* dst = g_attout + (size_t)b * CP * NPIX;
    #pragma unroll
    for (int ms = 0; ms < 2; ++ms)
        #pragma unroll
        for (int ng = 0; ng < 2; ++ng) {
            int row = mw * 32 + ms * 16 + (lane >> 2);
            int col = j0 + nw * 16 + ng * 8 + 2 * (lane & 3);
            *(float2*)(dst + (size_t)row * NPIX + col)       = make_float2(c[ms][ng][0], c[ms][ng][1]);
            *(float2*)(dst + (size_t)(row + 8) * NPIX + col) = make_float2(c[ms][ng][2], c[ms][ng][3]);
        }
}

// ---------------- final: y = gamma * (Wv_sn @ attout) + x ----------------
__global__ void final_kernel(const float* x, const float* gamma, float* y)
{
    int b  = blockIdx.z;
    int c0 = blockIdx.y * 64;
    int n0 = blockIdx.x * 64;
    const float* A  = g_Wv;
    const float* Bv = g_attout + (size_t)b * CP * NPIX;

    __shared__ float As[32][65];
    __shared__ float Bs[32][65];
    int tid = threadIdx.x;
    int ty = tid >> 4, tx = tid & 15;
    float acc[4][4] = {};

    for (int k0 = 0; k0 < 64; k0 += 32) {
        #pragma unroll
        for (int t = 0; t < 8; ++t) {
            int idx = tid + t * 256;
            int m = idx >> 5, k = idx & 31;
            As[k][m] = A[(c0 + m) * 64 + k0 + k];
        }
        #pragma unroll
        for (int t = 0; t < 8; ++t) {
            int idx = tid + t * 256;
            int k = idx >> 6, n = idx & 63;
            Bs[k][n] = Bv[(size_t)(k0 + k) * NPIX + n0 + n];
        }
        __syncthreads();
        #pragma unroll
        for (int kk = 0; kk < 32; ++kk) {
            float a[4], bb[4];
            #pragma unroll
            for (int i = 0; i < 4; ++i) { a[i] = As[kk][ty * 4 + i]; bb[i] = Bs[kk][tx * 4 + i]; }
            #pragma unroll
            for (int mi = 0; mi < 4; ++mi)
                #pragma unroll
                for (int ni = 0; ni < 4; ++ni)
                    acc[mi][ni] = fmaf(a[mi], bb[ni], acc[mi][ni]);
        }
        __syncthreads();
    }
    float g = gamma[0];
    #pragma unroll
    for (int mi = 0; mi < 4; ++mi)
        #pragma unroll
        for (int ni = 0; ni < 4; ++ni) {
            size_t o = (size_t)b * CIN * NPIX + (size_t)(c0 + ty * 4 + mi) * NPIX + n0 + tx * 4 + ni;
            y[o] = g * acc[mi][ni] + x[o];
        }
}

// ---------------- launch ----------------
extern "C" void kernel_launch(void* const* d_in, const int* in_sizes, int n_in,
                              void* d_out, int out_size)
{
    const float* x     = (const float*)d_in[0];
    const float* Wf    = (const float*)d_in[1];
    const float* Wg    = (const float*)d_in[2];
    const float* Wh    = (const float*)d_in[3];
    const float* Wv    = (const float*)d_in[4];
    const float* uf    = (const float*)d_in[5];
    const float* ug    = (const float*)d_in[6];
    const float* uh    = (const float*)d_in[7];
    const float* uv    = (const float*)d_in[8];
    const float* gamma = (const float*)d_in[9];
    float* y = (float*)d_out;

    spectral_kernel<<<4, 512>>>(Wf, Wg, Wh, Wv, uf, ug, uh, uv);
    proj_kernel<<<dim3(32, 4, 3), 256>>>(x);
    expz_kernel<<<dim3(64, 4), 256>>>();
    corr_kernel<<<8192, 256>>>();
    hscale_kernel<<<4096, 256>>>();
    pv_kernel<<<dim3(64, 4), 256>>>();
    final_kernel<<<dim3(64, 8, 4), 256>>>(x, gamma, y);
}